// round 4
// baseline (speedup 1.0000x reference)
#include <cuda_runtime.h>
#include <math.h>

#define G 2048
#define E 512
#define B 16

// ---------------- device scratch ----------------
__device__ float g_q0[E], g_q1[E], g_k0v[E], g_k1v[E];
__device__ float g_S[4];                      // S[a*2+c] = q_a . k_c
__device__ __align__(16) unsigned g_bits[G];  // bit b = xbin[b, g]
__device__ float g_lr3;
__device__ float g_upart[16 * G];             // partial u sums (per 128-row slab)
__device__ float g_u[G];                      // fcCox_w @ fc1_w

__device__ __forceinline__ float lrelu(float x) { return x > 0.f ? x : 0.01f * x; }

// ---------------- kernel 1: q/k projections + prep + u partials ----------
// blocks [0,512)   : q/k projections of the 2 embedding rows (f = block)
//                    blocks [0,16) also binarize datax into bitmasks
// blocks [512,768) : u partials: g_upart[p][g] = sum_{j in slab p} fcCox[j]*fc1w[j][g]
__global__ void qk_kernel(const float* __restrict__ embMat,
                          const float* __restrict__ Wq,
                          const float* __restrict__ Wk,
                          const int* __restrict__ datax,
                          const float* __restrict__ k3,
                          const float* __restrict__ fc1w,
                          const float* __restrict__ fcCox) {
    int tid = threadIdx.x;        // 128 threads
    int f = blockIdx.x;

    if (f >= 512) {               // ---- u partials ----
        int bu = f - 512;                     // 0..255
        int p  = bu >> 4;                     // 0..15 (slab of 128 fc1 rows)
        int gg = (bu & 15) * 128 + tid;       // 0..2047
        const float* base = fc1w + (size_t)p * 128 * G + gg;
        float acc = 0.f;
#pragma unroll 4
        for (int j = 0; j < 128; j++)
            acc += fcCox[p * 128 + j] * base[(size_t)j * G];
        g_upart[p * G + gg] = acc;
        return;
    }

    if (f < 16) {                 // ---- folded prep ----
        int g = f * 128 + tid;
        unsigned bits = 0;
#pragma unroll
        for (int b = 0; b < B; b++)
            bits |= (datax[b * G + g] != 0 ? 1u : 0u) << b;
        g_bits[g] = bits;
        if (f == 0 && tid == 0) g_lr3 = lrelu(k3[0]);
    }

    const float* wq = Wq + (size_t)f * E;
    const float* wk = Wk + (size_t)f * E;
    float s0q = 0.f, s1q = 0.f, s0k = 0.f, s1k = 0.f;
    for (int e = tid; e < E; e += 128) {
        float e0 = embMat[e], e1 = embMat[E + e];
        float wqe = wq[e], wke = wk[e];
        s0q += e0 * wqe; s1q += e1 * wqe;
        s0k += e0 * wke; s1k += e1 * wke;
    }
#pragma unroll
    for (int o = 16; o > 0; o >>= 1) {
        s0q += __shfl_down_sync(~0u, s0q, o);
        s1q += __shfl_down_sync(~0u, s1q, o);
        s0k += __shfl_down_sync(~0u, s0k, o);
        s1k += __shfl_down_sync(~0u, s1k, o);
    }
    __shared__ float red[4][4];
    int w = tid >> 5, l = tid & 31;
    if (l == 0) { red[w][0] = s0q; red[w][1] = s1q; red[w][2] = s0k; red[w][3] = s1k; }
    __syncthreads();
    if (tid == 0) {
        float a = 0, b = 0, c = 0, d = 0;
        for (int i = 0; i < 4; i++) { a += red[i][0]; b += red[i][1]; c += red[i][2]; d += red[i][3]; }
        g_q0[f] = a; g_q1[f] = b; g_k0v[f] = c; g_k1v[f] = d;
    }
}

// ---------------- kernel 2: S table + u reduce + out init ---------------
// block 0      : the 2x2 score table S  AND  out[b] = sum_g fc1b[g]*fcCox[g]
// blocks 1..8  : g_u[g] = sum_p g_upart[p][g]
__global__ void s_kernel(const float* __restrict__ fc1b,
                         const float* __restrict__ fcCox,
                         float* __restrict__ out) {
    int t = threadIdx.x;          // 512 threads

    if (blockIdx.x > 0) {         // ---- u reduce ----
        if (t < 256) {
            int g = (blockIdx.x - 1) * 256 + t;
            float s = 0.f;
#pragma unroll
            for (int p = 0; p < 16; p++) s += g_upart[p * G + g];
            g_u[g] = s;
        }
        return;
    }

    float q0 = g_q0[t], q1 = g_q1[t], k0 = g_k0v[t], k1 = g_k1v[t];
    float p0 = q0 * k0, p1 = q0 * k1, p2 = q1 * k0, p3 = q1 * k1;
    // bias-constant term of the output: C = sum_g fc1b[g]*fcCox[g]
    float c0 = 0.f;
#pragma unroll
    for (int i = 0; i < 4; i++) {
        int g = t + i * 512;
        c0 += fc1b[g] * fcCox[g];
    }
#pragma unroll
    for (int o = 16; o > 0; o >>= 1) {
        p0 += __shfl_down_sync(~0u, p0, o);
        p1 += __shfl_down_sync(~0u, p1, o);
        p2 += __shfl_down_sync(~0u, p2, o);
        p3 += __shfl_down_sync(~0u, p3, o);
        c0 += __shfl_down_sync(~0u, c0, o);
    }
    __shared__ float red[16][5];
    int w = t >> 5, l = t & 31;
    if (l == 0) { red[w][0] = p0; red[w][1] = p1; red[w][2] = p2; red[w][3] = p3; red[w][4] = c0; }
    __syncthreads();
    if (t == 0) {
        float a = 0, b = 0, c = 0, d = 0, e = 0;
        for (int i = 0; i < 16; i++) { a += red[i][0]; b += red[i][1]; c += red[i][2]; d += red[i][3]; e += red[i][4]; }
        g_S[0] = a; g_S[1] = b; g_S[2] = c; g_S[3] = d;
        red[0][4] = e;
    }
    __syncthreads();
    if (t < B) out[t] = red[0][4];   // init out[b] = C; big_kernel atomicAdds the rest
}

// ---------------- kernel 3: fused bias + origin write + softmax + output -
// one block per g-row; each thread owns 8 h values (2 float4) in registers.
__global__ void __launch_bounds__(256, 3)
big_kernel(const float* __restrict__ k1m, const float* __restrict__ k2m,
           const float* __restrict__ spm, const float* __restrict__ cmm,
           const float* __restrict__ padm, float* __restrict__ out) {
    int g = blockIdx.x;
    int tid = threadIdx.x;        // 256
    __shared__ float smax[8];
    __shared__ float sAcc[2 * B];
    __shared__ float sM;
    if (tid < 2 * B) sAcc[tid] = 0.f;

    unsigned gb = g_bits[g];
    float lr3 = g_lr3;
    float s00 = g_S[0], s01 = g_S[1], s10 = g_S[2], s11 = g_S[3];

    size_t rowoff = (size_t)g * G;
    const float4* r1 = (const float4*)(k1m + rowoff);
    const float4* r2 = (const float4*)(k2m + rowoff);
    const float4* rs = (const float4*)(spm + rowoff);
    const float4* rc = (const float4*)(cmm + rowoff);
    const float4* rp = (const float4*)(padm + rowoff);

    float4 bias[2];
    uint4 hb[2];
    float lmax = -3.4e38f;
#pragma unroll
    for (int i = 0; i < 2; i++) {
        int h4 = tid + i * 256;
        float4 v1 = __ldcs(&r1[h4]), v2 = __ldcs(&r2[h4]);
        float4 vs = __ldcs(&rs[h4]), vc = __ldcs(&rc[h4]), vp = __ldcs(&rp[h4]);
        float4 bv;
        bv.x = lrelu(v1.x) * vs.x + lrelu(v2.x) * vc.x + lr3 * vp.x;
        bv.y = lrelu(v1.y) * vs.y + lrelu(v2.y) * vc.y + lr3 * vp.y;
        bv.z = lrelu(v1.z) * vs.z + lrelu(v2.z) * vc.z + lr3 * vp.z;
        bv.w = lrelu(v1.w) * vs.w + lrelu(v2.w) * vc.w + lr3 * vp.w;
        bias[i] = bv;
        hb[i] = ((const uint4*)g_bits)[h4];
        lmax = fmaxf(lmax, fmaxf(fmaxf(bv.x, bv.y), fmaxf(bv.z, bv.w)));

        float* ob = out + 16 + rowoff + (size_t)h4 * 4;
#pragma unroll
        for (int b = 0; b < B; b++) {
            unsigned a = (gb >> b) & 1u;      // block-uniform
            float a0 = a ? s10 : s00;
            float a1 = a ? s11 : s01;
            float4 o;
            o.x = bv.x + (((hb[i].x >> b) & 1u) ? a1 : a0);
            o.y = bv.y + (((hb[i].y >> b) & 1u) ? a1 : a0);
            o.z = bv.z + (((hb[i].z >> b) & 1u) ? a1 : a0);
            o.w = bv.w + (((hb[i].w >> b) & 1u) ? a1 : a0);
            *((float4*)ob) = o;
            ob += (size_t)G * G;
        }
    }

    // block max of bias row
#pragma unroll
    for (int o = 16; o > 0; o >>= 1) lmax = fmaxf(lmax, __shfl_xor_sync(~0u, lmax, o));
    if ((tid & 31) == 0) smax[tid >> 5] = lmax;
    __syncthreads();
    if (tid == 0) {
        float m = smax[0];
        for (int i = 1; i < 8; i++) m = fmaxf(m, smax[i]);
        sM = m;
    }
    __syncthreads();
    float M = sM;

    // exps overwrite bias registers; per-b sequential accumulation.
    // T0 accumulated DIRECTLY (no tot - T1 subtraction -> no cancellation).
    float e[8];
    e[0] = __expf(bias[0].x - M); e[1] = __expf(bias[0].y - M);
    e[2] = __expf(bias[0].z - M); e[3] = __expf(bias[0].w - M);
    e[4] = __expf(bias[1].x - M); e[5] = __expf(bias[1].y - M);
    e[6] = __expf(bias[1].z - M); e[7] = __expf(bias[1].w - M);

#pragma unroll
    for (int b = 0; b < B; b++) {
        float m0 = ((hb[0].x >> b) & 1u) ? e[0] : 0.f;
        float m1 = ((hb[0].y >> b) & 1u) ? e[1] : 0.f;
        float m2 = ((hb[0].z >> b) & 1u) ? e[2] : 0.f;
        float m3 = ((hb[0].w >> b) & 1u) ? e[3] : 0.f;
        float m4 = ((hb[1].x >> b) & 1u) ? e[4] : 0.f;
        float m5 = ((hb[1].y >> b) & 1u) ? e[5] : 0.f;
        float m6 = ((hb[1].z >> b) & 1u) ? e[6] : 0.f;
        float m7 = ((hb[1].w >> b) & 1u) ? e[7] : 0.f;
        float t1 = ((m0 + m1) + (m2 + m3)) + ((m4 + m5) + (m6 + m7));
        float t0 = (((e[0] - m0) + (e[1] - m1)) + ((e[2] - m2) + (e[3] - m3)))
                 + (((e[4] - m4) + (e[5] - m5)) + ((e[6] - m6) + (e[7] - m7)));
#pragma unroll
        for (int o = 16; o > 0; o >>= 1) {
            t1 += __shfl_down_sync(~0u, t1, o);
            t0 += __shfl_down_sync(~0u, t0, o);
        }
        if ((tid & 31) == 0) {
            atomicAdd(&sAcc[b], t1);
            atomicAdd(&sAcc[B + b], t0);
        }
    }
    __syncthreads();

    // ---- fold the former final_kernel: this block's contribution to out[b]
    if (tid < B) {
        int b = tid;
        float T1 = sAcc[b];
        float T0 = sAcc[B + b];
        unsigned A = (gb >> b) & 1u;
        float sa0 = A ? s10 : s00;
        float sa1 = A ? s11 : s01;
        float mm = fmaxf(sa0, sa1);
        float f0 = __expf(sa0 - mm);
        float f1 = __expf(sa1 - mm);
        float num = f1 * T1;
        float den = f0 * T0 + num;
        float y = (float)A + num / den;
        atomicAdd(&out[b], y * g_u[g]);
    }
}

// ---------------- launch ----------------
extern "C" void kernel_launch(void* const* d_in, const int* in_sizes, int n_in,
                              void* d_out, int out_size) {
    const int*   datax  = (const int*)d_in[0];
    const float* embMat = (const float*)d_in[1];
    const float* Wq     = (const float*)d_in[2];
    const float* Wk     = (const float*)d_in[3];
    const float* k1     = (const float*)d_in[4];
    const float* k2     = (const float*)d_in[5];
    const float* k3     = (const float*)d_in[6];
    const float* sp     = (const float*)d_in[7];
    const float* cm     = (const float*)d_in[8];
    const float* pad    = (const float*)d_in[9];
    const float* fc1w   = (const float*)d_in[10];
    const float* fc1b   = (const float*)d_in[11];
    const float* fcCox  = (const float*)d_in[12];
    float* out = (float*)d_out;

    qk_kernel<<<768, 128>>>(embMat, Wq, Wk, datax, k3, fc1w, fcCox);
    s_kernel<<<9, 512>>>(fc1b, fcCox, out);
    big_kernel<<<G, 256>>>(k1, k2, sp, cm, pad, out);
}

// round 5
// speedup vs baseline: 1.3746x; 1.3746x over previous
#include <cuda_runtime.h>
#include <math.h>

#define G 2048
#define E 512
#define B 16

// ---------------- device scratch ----------------
__device__ float g_q0[E], g_q1[E], g_k0v[E], g_k1v[E];
__device__ float g_S[4];                      // S[a*2+c] = q_a . k_c
__device__ __align__(16) unsigned g_bits[G];  // bit b = xbin[b, g]
__device__ float g_lr3;
__device__ float g_upart[16 * G];             // u partials (16 slabs of 128 rows)
__device__ float g_u[G];                      // fcCox_w @ fc1_w

__device__ __forceinline__ float lrelu(float x) { return x > 0.f ? x : 0.01f * x; }

// ---------------- kernel 1: qk projections + prep + u partials -----------
// 256 threads/block.
// blocks [0,512)   : q/k projections (f = blockIdx); blocks [0,8) also prep
// blocks [512,640) : u partials over fc1w slabs (16 MB read, the bulk)
__global__ void qk_kernel(const float* __restrict__ embMat,
                          const float* __restrict__ Wq,
                          const float* __restrict__ Wk,
                          const int* __restrict__ datax,
                          const float* __restrict__ k3,
                          const float* __restrict__ fc1w,
                          const float* __restrict__ fcCox) {
    int tid = threadIdx.x;        // 256
    int f = blockIdx.x;

    if (f >= 512) {               // ---- u partials: 128 blocks ----
        int bu = f - 512;                     // 0..127
        int gg = (bu & 7) * 256 + tid;        // 0..2047
        int p  = bu >> 3;                     // 0..15 slab of 128 fc1 rows
        const float* base = fc1w + (size_t)p * 128 * G + gg;
        const float* cw = fcCox + p * 128;
        float acc = 0.f;
#pragma unroll 8
        for (int j = 0; j < 128; j++)
            acc += cw[j] * base[(size_t)j * G];
        g_upart[p * G + gg] = acc;
        return;
    }

    if (f < 8) {                  // ---- folded prep ----
        int g = f * 256 + tid;
        unsigned bits = 0;
#pragma unroll
        for (int b = 0; b < B; b++)
            bits |= (datax[b * G + g] != 0 ? 1u : 0u) << b;
        g_bits[g] = bits;
        if (f == 0 && tid == 0) g_lr3 = lrelu(k3[0]);
    }

    // ---- q/k projection for feature f ----
    const float* wq = Wq + (size_t)f * E;
    const float* wk = Wk + (size_t)f * E;
    float s0q = 0.f, s1q = 0.f, s0k = 0.f, s1k = 0.f;
#pragma unroll
    for (int i = 0; i < 2; i++) {
        int e = tid + i * 256;
        float e0 = embMat[e], e1 = embMat[E + e];
        float wqe = wq[e], wke = wk[e];
        s0q += e0 * wqe; s1q += e1 * wqe;
        s0k += e0 * wke; s1k += e1 * wke;
    }
#pragma unroll
    for (int o = 16; o > 0; o >>= 1) {
        s0q += __shfl_down_sync(~0u, s0q, o);
        s1q += __shfl_down_sync(~0u, s1q, o);
        s0k += __shfl_down_sync(~0u, s0k, o);
        s1k += __shfl_down_sync(~0u, s1k, o);
    }
    __shared__ float red[8][4];
    int w = tid >> 5, l = tid & 31;
    if (l == 0) { red[w][0] = s0q; red[w][1] = s1q; red[w][2] = s0k; red[w][3] = s1k; }
    __syncthreads();
    if (tid == 0) {
        float a = 0, b = 0, c = 0, d = 0;
        for (int i = 0; i < 8; i++) { a += red[i][0]; b += red[i][1]; c += red[i][2]; d += red[i][3]; }
        g_q0[f] = a; g_q1[f] = b; g_k0v[f] = c; g_k1v[f] = d;
    }
}

// ---------------- kernel 2: S table + C + u reduce -----------------------
// block 0      : 2x2 score table S, C = sum fc1b*fcCox, out init
// blocks 1..8  : g_u[g] = sum_p g_upart[p][g]
__global__ void s_kernel(const float* __restrict__ fc1b,
                         const float* __restrict__ fcCox,
                         float* __restrict__ out) {
    int t = threadIdx.x;          // 512

    if (blockIdx.x > 0) {         // ---- u reduce ----
        if (t < 256) {
            int g = (blockIdx.x - 1) * 256 + t;
            float s = 0.f;
#pragma unroll
            for (int p = 0; p < 16; p++) s += g_upart[p * G + g];
            g_u[g] = s;
        }
        return;
    }

    float q0 = g_q0[t], q1 = g_q1[t], k0 = g_k0v[t], k1 = g_k1v[t];
    float p0 = q0 * k0, p1 = q0 * k1, p2 = q1 * k0, p3 = q1 * k1;
    float c0 = 0.f;
#pragma unroll
    for (int i = 0; i < 4; i++) {
        int g = t + i * 512;
        c0 += fc1b[g] * fcCox[g];
    }
#pragma unroll
    for (int o = 16; o > 0; o >>= 1) {
        p0 += __shfl_down_sync(~0u, p0, o);
        p1 += __shfl_down_sync(~0u, p1, o);
        p2 += __shfl_down_sync(~0u, p2, o);
        p3 += __shfl_down_sync(~0u, p3, o);
        c0 += __shfl_down_sync(~0u, c0, o);
    }
    __shared__ float red[16][5];
    int w = t >> 5, l = t & 31;
    if (l == 0) { red[w][0] = p0; red[w][1] = p1; red[w][2] = p2; red[w][3] = p3; red[w][4] = c0; }
    __syncthreads();
    if (t == 0) {
        float a = 0, b = 0, c = 0, d = 0, e = 0;
        for (int i = 0; i < 16; i++) { a += red[i][0]; b += red[i][1]; c += red[i][2]; d += red[i][3]; e += red[i][4]; }
        g_S[0] = a; g_S[1] = b; g_S[2] = c; g_S[3] = d;
        red[0][4] = e;
    }
    __syncthreads();
    if (t < B) out[t] = red[0][4];   // out[b] = C; big_kernel atomicAdds the rest
}

// ---------------- kernel 3: fused bias + origin write + softmax + output -
// EXACT R2 body (the measured-fastest config: launch_bounds(256,2), plain
// loads/stores, array accumulators) plus the cheap output tail fold.
__global__ void __launch_bounds__(256, 2)
big_kernel(const float* __restrict__ k1m, const float* __restrict__ k2m,
           const float* __restrict__ spm, const float* __restrict__ cmm,
           const float* __restrict__ padm, float* __restrict__ out) {
    int g = blockIdx.x;
    int tid = threadIdx.x;        // 256
    __shared__ float smax[8];
    __shared__ float sAcc[2 * B];
    __shared__ float sM;
    if (tid < 2 * B) sAcc[tid] = 0.f;

    unsigned gb = g_bits[g];
    float lr3 = g_lr3;
    float s00 = g_S[0], s01 = g_S[1], s10 = g_S[2], s11 = g_S[3];

    size_t rowoff = (size_t)g * G;
    const float4* r1 = (const float4*)(k1m + rowoff);
    const float4* r2 = (const float4*)(k2m + rowoff);
    const float4* rs = (const float4*)(spm + rowoff);
    const float4* rc = (const float4*)(cmm + rowoff);
    const float4* rp = (const float4*)(padm + rowoff);

    float4 bias[2];
    uint4 hb[2];
    float lmax = -3.4e38f;
#pragma unroll
    for (int i = 0; i < 2; i++) {
        int h4 = tid + i * 256;
        float4 v1 = r1[h4], v2 = r2[h4], vs = rs[h4], vc = rc[h4], vp = rp[h4];
        float4 bv;
        bv.x = lrelu(v1.x) * vs.x + lrelu(v2.x) * vc.x + lr3 * vp.x;
        bv.y = lrelu(v1.y) * vs.y + lrelu(v2.y) * vc.y + lr3 * vp.y;
        bv.z = lrelu(v1.z) * vs.z + lrelu(v2.z) * vc.z + lr3 * vp.z;
        bv.w = lrelu(v1.w) * vs.w + lrelu(v2.w) * vc.w + lr3 * vp.w;
        bias[i] = bv;
        hb[i] = ((const uint4*)g_bits)[h4];
        lmax = fmaxf(lmax, fmaxf(fmaxf(bv.x, bv.y), fmaxf(bv.z, bv.w)));
        float* obase = out + 16 + rowoff + (size_t)h4 * 4;
#pragma unroll
        for (int b = 0; b < B; b++) {
            int a = (gb >> b) & 1;
            float a0 = a ? s10 : s00;
            float a1 = a ? s11 : s01;
            float4 o;
            o.x = bv.x + (((hb[i].x >> b) & 1) ? a1 : a0);
            o.y = bv.y + (((hb[i].y >> b) & 1) ? a1 : a0);
            o.z = bv.z + (((hb[i].z >> b) & 1) ? a1 : a0);
            o.w = bv.w + (((hb[i].w >> b) & 1) ? a1 : a0);
            *((float4*)(obase + (size_t)b * ((size_t)G * G))) = o;
        }
    }

    // block max of bias row
#pragma unroll
    for (int o = 16; o > 0; o >>= 1) lmax = fmaxf(lmax, __shfl_xor_sync(~0u, lmax, o));
    if ((tid & 31) == 0) smax[tid >> 5] = lmax;
    __syncthreads();
    if (tid == 0) {
        float m = smax[0];
        for (int i = 1; i < 8; i++) m = fmaxf(m, smax[i]);
        sM = m;
    }
    __syncthreads();
    float M = sM;

    float t1[B], t0[B];
#pragma unroll
    for (int b = 0; b < B; b++) { t1[b] = 0.f; t0[b] = 0.f; }
#pragma unroll
    for (int i = 0; i < 2; i++) {
        float e0 = __expf(bias[i].x - M);
        float e1 = __expf(bias[i].y - M);
        float e2 = __expf(bias[i].z - M);
        float e3 = __expf(bias[i].w - M);
#pragma unroll
        for (int b = 0; b < B; b++) {
            float m0 = ((hb[i].x >> b) & 1) ? e0 : 0.f;
            float m1 = ((hb[i].y >> b) & 1) ? e1 : 0.f;
            float m2 = ((hb[i].z >> b) & 1) ? e2 : 0.f;
            float m3 = ((hb[i].w >> b) & 1) ? e3 : 0.f;
            t1[b] += (m0 + m1) + (m2 + m3);
            t0[b] += ((e0 - m0) + (e1 - m1)) + ((e2 - m2) + (e3 - m3));
        }
    }
#pragma unroll
    for (int o = 16; o > 0; o >>= 1) {
#pragma unroll
        for (int b = 0; b < B; b++) {
            t1[b] += __shfl_down_sync(~0u, t1[b], o);
            t0[b] += __shfl_down_sync(~0u, t0[b], o);
        }
    }
    if ((tid & 31) == 0) {
#pragma unroll
        for (int b = 0; b < B; b++) {
            atomicAdd(&sAcc[b], t1[b]);
            atomicAdd(&sAcc[B + b], t0[b]);
        }
    }
    __syncthreads();

    // ---- output tail: this row's contribution to out[b] ----
    if (tid < B) {
        int b = tid;
        float T1 = sAcc[b];
        float T0 = sAcc[B + b];
        unsigned A = (gb >> b) & 1u;
        float sa0 = A ? s10 : s00;
        float sa1 = A ? s11 : s01;
        float mm = fmaxf(sa0, sa1);
        float f0 = __expf(sa0 - mm);
        float f1 = __expf(sa1 - mm);
        float num = f1 * T1;
        float den = f0 * T0 + num;
        float y = (float)A + num / den;
        atomicAdd(&out[b], y * g_u[g]);
    }
}

// ---------------- launch ----------------
extern "C" void kernel_launch(void* const* d_in, const int* in_sizes, int n_in,
                              void* d_out, int out_size) {
    const int*   datax  = (const int*)d_in[0];
    const float* embMat = (const float*)d_in[1];
    const float* Wq     = (const float*)d_in[2];
    const float* Wk     = (const float*)d_in[3];
    const float* k1     = (const float*)d_in[4];
    const float* k2     = (const float*)d_in[5];
    const float* k3     = (const float*)d_in[6];
    const float* sp     = (const float*)d_in[7];
    const float* cm     = (const float*)d_in[8];
    const float* pad    = (const float*)d_in[9];
    const float* fc1w   = (const float*)d_in[10];
    const float* fc1b   = (const float*)d_in[11];
    const float* fcCox  = (const float*)d_in[12];
    float* out = (float*)d_out;

    qk_kernel<<<640, 256>>>(embMat, Wq, Wk, datax, k3, fc1w, fcCox);
    s_kernel<<<9, 512>>>(fc1b, fcCox, out);
    big_kernel<<<G, 256>>>(k1, k2, sp, cm, pad, out);
}